// round 2
// baseline (speedup 1.0000x reference)
#include <cuda_runtime.h>

#define NN 100000
#define EE 1600000
#define ET (EE + NN)
#define GG 2048
#define ENC_NEG 0x007FFFFFu  /* enc(-inf) */

// ---------------- scratch (device globals; no allocation) ----------------
__device__ __align__(16) float    g_H[(size_t)NN * 64];   // transformed features
__device__ __align__(16) float    g_A[(size_t)NN * 64];   // aggregated output
__device__ __align__(16) float    g_als[NN * 4];
__device__ __align__(16) float    g_ald[NN * 4];
__device__ __align__(16) unsigned g_menc[NN * 4];         // encoded float max
__device__ __align__(16) float    g_ssum[NN * 4];
__device__ int g_src[ET];
__device__ int g_dst[ET];

// monotone float<->uint encoding so atomicMax(unsigned) == float max
__device__ __forceinline__ unsigned fenc(float f) {
    unsigned u = __float_as_uint(f);
    return (u & 0x80000000u) ? ~u : (u | 0x80000000u);
}
__device__ __forceinline__ float fdec(unsigned u) {
    return (u & 0x80000000u) ? __uint_as_float(u ^ 0x80000000u)
                             : __uint_as_float(~u);
}
__device__ __forceinline__ float lrelu(float x) { return x > 0.f ? x : 0.2f * x; }

// ---------------- edge prep: copy int32 indices, append self-loops ----------------
__global__ void prep_edges_kernel(const int* __restrict__ ei) {
    int i = blockIdx.x * blockDim.x + threadIdx.x;
    if (i >= ET) return;
    if (i < EE) {
        g_src[i] = ei[i];
        g_dst[i] = ei[EE + i];
    } else {
        g_src[i] = i - EE;
        g_dst[i] = i - EE;
    }
}

// ---------------- fused GEMM + attention logits + per-node init ----------------
// h = act(xin) @ W ; als/ald = einsum(h, a_src/a_dst); init menc/ssum/A
// FROM_A: read input from g_A (layers 1,2), applying prev bias + relu.
template <int FIN, bool FROM_A>
__global__ void __launch_bounds__(128)
gemm_attn_kernel(const float* xin_ext,
                 const float* __restrict__ W,
                 const float* __restrict__ a_src,
                 const float* __restrict__ a_dst,
                 const float* __restrict__ pbias) {
    __shared__ float Ws[FIN * 64];
    __shared__ float As[64], Ad[64];
    __shared__ float Pb[FIN];
    int tid = threadIdx.x;
    for (int i = tid; i < FIN * 64; i += 128) Ws[i] = W[i];
    if (tid < 64) { As[tid] = a_src[tid]; Ad[tid] = a_dst[tid]; }
    if (FROM_A) {
        for (int i = tid; i < FIN; i += 128) Pb[i] = pbias[i];
    }
    __syncthreads();

    int n = blockIdx.x * 128 + tid;
    if (n >= NN) return;

    float acc[64];
#pragma unroll
    for (int j = 0; j < 64; j++) acc[j] = 0.f;

    // NOTE: when FROM_A, input aliases g_A; each thread reads only its own
    // row and zeroes only its own row afterwards — no cross-thread hazard.
    const float* xin = FROM_A ? (const float*)g_A : xin_ext;
    const float4* xr = reinterpret_cast<const float4*>(xin + (size_t)n * FIN);

    for (int k4 = 0; k4 < FIN / 4; k4++) {
        float4 xv = xr[k4];
        float xs[4] = {xv.x, xv.y, xv.z, xv.w};
#pragma unroll
        for (int u = 0; u < 4; u++) {
            float v = xs[u];
            if (FROM_A) v = fmaxf(v + Pb[k4 * 4 + u], 0.f);
            const float* wrow = &Ws[(k4 * 4 + u) * 64];
#pragma unroll
            for (int j = 0; j < 64; j++) acc[j] = fmaf(v, wrow[j], acc[j]);
        }
    }

    // write H (vectorized)
    float4* Hr = reinterpret_cast<float4*>(g_H + (size_t)n * 64);
#pragma unroll
    for (int j4 = 0; j4 < 16; j4++)
        Hr[j4] = make_float4(acc[4 * j4], acc[4 * j4 + 1], acc[4 * j4 + 2], acc[4 * j4 + 3]);

    // attention logits + per-node softmax-state init
#pragma unroll
    for (int h = 0; h < 4; h++) {
        float ss = 0.f, dd = 0.f;
#pragma unroll
        for (int c = 0; c < 16; c++) {
            ss = fmaf(acc[h * 16 + c], As[h * 16 + c], ss);
            dd = fmaf(acc[h * 16 + c], Ad[h * 16 + c], dd);
        }
        g_als[n * 4 + h] = ss;
        g_ald[n * 4 + h] = dd;
        g_menc[n * 4 + h] = ENC_NEG;
        g_ssum[n * 4 + h] = 0.f;
    }

    // zero aggregation buffer for this layer (after input row fully read)
    float4* Ar = reinterpret_cast<float4*>(g_A + (size_t)n * 64);
#pragma unroll
    for (int j4 = 0; j4 < 16; j4++) Ar[j4] = make_float4(0.f, 0.f, 0.f, 0.f);
}

// ---------------- edge pass 1: segment max ----------------
__global__ void edge_max_kernel() {
    int e = blockIdx.x * blockDim.x + threadIdx.x;
    if (e >= ET) return;
    int sn = g_src[e], dn = g_dst[e];
    float4 a = *reinterpret_cast<const float4*>(g_als + sn * 4);
    float4 b = *reinterpret_cast<const float4*>(g_ald + dn * 4);
    unsigned* mp = g_menc + dn * 4;
    atomicMax(mp + 0, fenc(lrelu(a.x + b.x)));
    atomicMax(mp + 1, fenc(lrelu(a.y + b.y)));
    atomicMax(mp + 2, fenc(lrelu(a.z + b.z)));
    atomicMax(mp + 3, fenc(lrelu(a.w + b.w)));
}

// ---------------- edge pass 2: segment sum of exp ----------------
__global__ void edge_sum_kernel() {
    int e = blockIdx.x * blockDim.x + threadIdx.x;
    if (e >= ET) return;
    int sn = g_src[e], dn = g_dst[e];
    float4 a = *reinterpret_cast<const float4*>(g_als + sn * 4);
    float4 b = *reinterpret_cast<const float4*>(g_ald + dn * 4);
    uint4 mu = *reinterpret_cast<const uint4*>(g_menc + dn * 4);
    float* sp = g_ssum + dn * 4;
    atomicAdd(sp + 0, __expf(lrelu(a.x + b.x) - fdec(mu.x)));
    atomicAdd(sp + 1, __expf(lrelu(a.y + b.y) - fdec(mu.y)));
    atomicAdd(sp + 2, __expf(lrelu(a.z + b.z) - fdec(mu.z)));
    atomicAdd(sp + 3, __expf(lrelu(a.w + b.w) - fdec(mu.w)));
}

// ---------------- edge pass 3: weighted scatter of messages ----------------
// 16 threads per edge, each handles 4 consecutive channels (float4 of h[src]).
__global__ void edge_agg_kernel() {
    long long t = (long long)blockIdx.x * blockDim.x + threadIdx.x;
    int e = (int)(t >> 4);
    int q = (int)(t & 15);
    if (e >= ET) return;
    int sn = g_src[e], dn = g_dst[e];
    int head = q >> 2;

    float lg = lrelu(g_als[sn * 4 + head] + g_ald[dn * 4 + head]);
    float m = fdec(g_menc[dn * 4 + head]);
    float s = g_ssum[dn * 4 + head];
    float alpha = __expf(lg - m) / (s + 1e-16f);

    float4 hv = reinterpret_cast<const float4*>(g_H)[(size_t)sn * 16 + q];
    float* o = g_A + (size_t)dn * 64 + q * 4;
    atomicAdd(o + 0, hv.x * alpha);
    atomicAdd(o + 1, hv.y * alpha);
    atomicAdd(o + 2, hv.z * alpha);
    atomicAdd(o + 3, hv.w * alpha);
}

// ---------------- output init + pooling + head ----------------
__global__ void init_out_kernel(float* out, const float* __restrict__ hb) {
    int g = blockIdx.x * blockDim.x + threadIdx.x;
    if (g < GG) out[g] = hb[0];
}

__global__ void pool_kernel(const float* __restrict__ b2,
                            const float* __restrict__ hw,
                            const int* __restrict__ batch,
                            float* out) {
    __shared__ float sb[64], sw[64];
    int tid = threadIdx.x;
    if (tid < 64) { sb[tid] = b2[tid]; sw[tid] = hw[tid]; }
    __syncthreads();

    long long t = (long long)blockIdx.x * blockDim.x + tid;
    int n = (int)(t >> 5);
    int lane = (int)(t & 31);
    if (n >= NN) return;

    const float* ar = g_A + (size_t)n * 64;
    float sm = fmaxf(ar[lane] + sb[lane], 0.f) * sw[lane]
             + fmaxf(ar[lane + 32] + sb[lane + 32], 0.f) * sw[lane + 32];
#pragma unroll
    for (int off = 16; off > 0; off >>= 1)
        sm += __shfl_down_sync(0xFFFFFFFFu, sm, off);
    if (lane == 0) atomicAdd(&out[(int)batch[n]], sm);
}

// ---------------- launch ----------------
extern "C" void kernel_launch(void* const* d_in, const int* in_sizes, int n_in,
                              void* d_out, int out_size) {
    const float* x     = (const float*)d_in[0];
    const int*   ei    = (const int*)d_in[1];    // JAX x64 disabled -> int32
    const int*   batch = (const int*)d_in[2];
    const float* W0  = (const float*)d_in[3];
    const float* as0 = (const float*)d_in[4];
    const float* ad0 = (const float*)d_in[5];
    const float* b0  = (const float*)d_in[6];
    const float* W1  = (const float*)d_in[7];
    const float* as1 = (const float*)d_in[8];
    const float* ad1 = (const float*)d_in[9];
    const float* b1  = (const float*)d_in[10];
    const float* W2  = (const float*)d_in[11];
    const float* as2 = (const float*)d_in[12];
    const float* ad2 = (const float*)d_in[13];
    const float* b2  = (const float*)d_in[14];
    const float* hw  = (const float*)d_in[15];
    const float* hb  = (const float*)d_in[16];
    float* out = (float*)d_out;

    const int EB  = (ET + 255) / 256;
    const int AGB = (int)(((long long)ET * 16 + 255) / 256);
    const int GB  = (NN + 127) / 128;
    const int PB  = (int)(((long long)NN * 32 + 255) / 256);

    prep_edges_kernel<<<EB, 256>>>(ei);

    // layer 0
    gemm_attn_kernel<128, false><<<GB, 128>>>(x, W0, as0, ad0, nullptr);
    edge_max_kernel<<<EB, 256>>>();
    edge_sum_kernel<<<EB, 256>>>();
    edge_agg_kernel<<<AGB, 256>>>();

    // layer 1 (input = g_A with bias b0 + relu)
    gemm_attn_kernel<64, true><<<GB, 128>>>(nullptr, W1, as1, ad1, b0);
    edge_max_kernel<<<EB, 256>>>();
    edge_sum_kernel<<<EB, 256>>>();
    edge_agg_kernel<<<AGB, 256>>>();

    // layer 2 (input = g_A with bias b1 + relu)
    gemm_attn_kernel<64, true><<<GB, 128>>>(nullptr, W2, as2, ad2, b1);
    edge_max_kernel<<<EB, 256>>>();
    edge_sum_kernel<<<EB, 256>>>();
    edge_agg_kernel<<<AGB, 256>>>();

    // pooling + head (bias b2 + relu fused here)
    init_out_kernel<<<(GG + 255) / 256, 256>>>(out, hb);
    pool_kernel<<<PB, 256>>>(b2, hw, batch, out);
}

// round 3
// speedup vs baseline: 2.7223x; 2.7223x over previous
#include <cuda_runtime.h>

#define NN 100000
#define EE 1600000
#define ET (EE + NN)
#define GG 2048
#define NBLK ((NN + 1023) / 1024)
#define WPB 8

// ---------------- scratch (device globals; no allocation) ----------------
__device__ __align__(16) float g_H[(size_t)NN * 64];   // transformed features
__device__ __align__(16) float g_A[(size_t)NN * 64];   // aggregated output
__device__ __align__(16) float g_als[NN * 4];
__device__ __align__(16) float g_ald[NN * 4];
__device__ int g_deg[NN];
__device__ int g_scan[NN];
__device__ int g_rowptr[NN];
__device__ int g_cursor[NN];
__device__ int g_bsum[NBLK];
__device__ int g_boff[NBLK];
__device__ int g_csrc[ET];

__device__ __forceinline__ float lrelu(float x) { return x > 0.f ? x : 0.2f * x; }

// ---------------- CSR build ----------------
__global__ void zero_deg_kernel() {
    int i = blockIdx.x * blockDim.x + threadIdx.x;
    if (i < NN) g_deg[i] = 0;
}

__global__ void hist_kernel(const int* __restrict__ ei) {
    int i = blockIdx.x * blockDim.x + threadIdx.x;
    if (i >= ET) return;
    int dst = (i < EE) ? ei[EE + i] : (i - EE);
    atomicAdd(&g_deg[dst], 1);
}

__global__ void scan1_kernel() {
    __shared__ int buf[1024];
    int t = threadIdx.x;
    int i = blockIdx.x * 1024 + t;
    int v = (i < NN) ? g_deg[i] : 0;
    buf[t] = v;
    __syncthreads();
    for (int off = 1; off < 1024; off <<= 1) {
        int add = (t >= off) ? buf[t - off] : 0;
        __syncthreads();
        buf[t] += add;
        __syncthreads();
    }
    if (i < NN) g_scan[i] = buf[t];
    if (t == 1023) g_bsum[blockIdx.x] = buf[1023];
}

__global__ void scan2_kernel() {
    if (threadIdx.x == 0) {
        int run = 0;
        for (int b = 0; b < NBLK; b++) { g_boff[b] = run; run += g_bsum[b]; }
    }
}

__global__ void scan3_kernel() {
    int i = blockIdx.x * blockDim.x + threadIdx.x;
    if (i >= NN) return;
    int rp = g_scan[i] - g_deg[i] + g_boff[i >> 10];  // exclusive prefix
    g_rowptr[i] = rp;
    g_cursor[i] = rp;
}

__global__ void scatter_kernel(const int* __restrict__ ei) {
    int i = blockIdx.x * blockDim.x + threadIdx.x;
    if (i >= ET) return;
    int src, dst;
    if (i < EE) { src = ei[i]; dst = ei[EE + i]; }
    else        { src = i - EE; dst = i - EE; }
    int pos = atomicAdd(&g_cursor[dst], 1);
    g_csrc[pos] = src;
}

// ---------------- fused GEMM + attention logits ----------------
// h = act(xin) @ W ; als/ald = einsum(h, a_src/a_dst)
template <int FIN, bool FROM_A>
__global__ void __launch_bounds__(128)
gemm_attn_kernel(const float* __restrict__ xin_ext,
                 const float* __restrict__ W,
                 const float* __restrict__ a_src,
                 const float* __restrict__ a_dst,
                 const float* __restrict__ pbias) {
    __shared__ float Ws[FIN * 64];
    __shared__ float As[64], Ad[64];
    __shared__ float Pb[FIN];
    int tid = threadIdx.x;
    for (int i = tid; i < FIN * 64; i += 128) Ws[i] = W[i];
    if (tid < 64) { As[tid] = a_src[tid]; Ad[tid] = a_dst[tid]; }
    if (FROM_A) {
        for (int i = tid; i < FIN; i += 128) Pb[i] = pbias[i];
    }
    __syncthreads();

    int n = blockIdx.x * 128 + tid;
    if (n >= NN) return;

    float acc[64];
#pragma unroll
    for (int j = 0; j < 64; j++) acc[j] = 0.f;

    const float* xin = FROM_A ? (const float*)g_A : xin_ext;
    const float4* xr = reinterpret_cast<const float4*>(xin + (size_t)n * FIN);

    for (int k4 = 0; k4 < FIN / 4; k4++) {
        float4 xv = xr[k4];
        float xs[4] = {xv.x, xv.y, xv.z, xv.w};
#pragma unroll
        for (int u = 0; u < 4; u++) {
            float v = xs[u];
            if (FROM_A) v = fmaxf(v + Pb[k4 * 4 + u], 0.f);
            const float* wrow = &Ws[(k4 * 4 + u) * 64];
#pragma unroll
            for (int j = 0; j < 64; j++) acc[j] = fmaf(v, wrow[j], acc[j]);
        }
    }

    float4* Hr = reinterpret_cast<float4*>(g_H + (size_t)n * 64);
#pragma unroll
    for (int j4 = 0; j4 < 16; j4++)
        Hr[j4] = make_float4(acc[4 * j4], acc[4 * j4 + 1], acc[4 * j4 + 2], acc[4 * j4 + 3]);

#pragma unroll
    for (int h = 0; h < 4; h++) {
        float ss = 0.f, dd = 0.f;
#pragma unroll
        for (int c = 0; c < 16; c++) {
            ss = fmaf(acc[h * 16 + c], As[h * 16 + c], ss);
            dd = fmaf(acc[h * 16 + c], Ad[h * 16 + c], dd);
        }
        g_als[n * 4 + h] = ss;
        g_ald[n * 4 + h] = dd;
    }
}

// ---------------- fused softmax + aggregation (gather, warp per dst node) ----
// m[h] = lrelu(max_src als[src][h] + ald[n][h])   (monotonicity of lrelu/+)
// out[n] = sum_e exp(lg-m)*h[src] / (sum_e exp(lg-m) + 1e-16)
__global__ void __launch_bounds__(256) gat_aggregate_kernel() {
    __shared__ int    s_s[WPB][32];
    __shared__ float4 s_w[WPB][32];

    int w = threadIdx.x >> 5;
    int lane = threadIdx.x & 31;
    int n = blockIdx.x * WPB + w;
    if (n >= NN) return;

    int beg = g_rowptr[n];
    int deg = g_deg[n];
    float4 ad = *reinterpret_cast<const float4*>(g_ald + n * 4);

    // phase 1: max of als[src] per head (lane-strided)
    float4 mx = make_float4(-1e30f, -1e30f, -1e30f, -1e30f);
    for (int i = lane; i < deg; i += 32) {
        int s = g_csrc[beg + i];
        float4 a = *reinterpret_cast<const float4*>(g_als + s * 4);
        mx.x = fmaxf(mx.x, a.x); mx.y = fmaxf(mx.y, a.y);
        mx.z = fmaxf(mx.z, a.z); mx.w = fmaxf(mx.w, a.w);
    }
#pragma unroll
    for (int off = 16; off; off >>= 1) {
        mx.x = fmaxf(mx.x, __shfl_xor_sync(0xFFFFFFFFu, mx.x, off));
        mx.y = fmaxf(mx.y, __shfl_xor_sync(0xFFFFFFFFu, mx.y, off));
        mx.z = fmaxf(mx.z, __shfl_xor_sync(0xFFFFFFFFu, mx.z, off));
        mx.w = fmaxf(mx.w, __shfl_xor_sync(0xFFFFFFFFu, mx.w, off));
    }
    float m0 = lrelu(mx.x + ad.x), m1 = lrelu(mx.y + ad.y);
    float m2 = lrelu(mx.z + ad.z), m3 = lrelu(mx.w + ad.w);

    // phase 2: chunked exp-weights + channel-parallel accumulation
    int head = lane >> 3;       // lane handles channels (2*lane, 2*lane+1)
    int cbase = 2 * lane;
    float accx = 0.f, accy = 0.f;
    float4 sw = make_float4(0.f, 0.f, 0.f, 0.f);

    for (int base = 0; base < deg; base += 32) {
        int i = base + lane;
        if (i < deg) {
            int s = g_csrc[beg + i];
            float4 a = *reinterpret_cast<const float4*>(g_als + s * 4);
            float4 wv;
            wv.x = __expf(lrelu(a.x + ad.x) - m0);
            wv.y = __expf(lrelu(a.y + ad.y) - m1);
            wv.z = __expf(lrelu(a.z + ad.z) - m2);
            wv.w = __expf(lrelu(a.w + ad.w) - m3);
            sw.x += wv.x; sw.y += wv.y; sw.z += wv.z; sw.w += wv.w;
            s_s[w][lane] = s;
            s_w[w][lane] = wv;
        }
        __syncwarp();
        int cnt = min(32, deg - base);
        const float* wp = reinterpret_cast<const float*>(&s_w[w][0]);
        int j = 0;
        for (; j + 4 <= cnt; j += 4) {
            int s0 = s_s[w][j + 0], s1 = s_s[w][j + 1];
            int s2 = s_s[w][j + 2], s3 = s_s[w][j + 3];
            float w0 = wp[(j + 0) * 4 + head], w1 = wp[(j + 1) * 4 + head];
            float w2 = wp[(j + 2) * 4 + head], w3 = wp[(j + 3) * 4 + head];
            float2 h0 = *reinterpret_cast<const float2*>(g_H + (size_t)s0 * 64 + cbase);
            float2 h1 = *reinterpret_cast<const float2*>(g_H + (size_t)s1 * 64 + cbase);
            float2 h2 = *reinterpret_cast<const float2*>(g_H + (size_t)s2 * 64 + cbase);
            float2 h3 = *reinterpret_cast<const float2*>(g_H + (size_t)s3 * 64 + cbase);
            accx = fmaf(w0, h0.x, accx); accy = fmaf(w0, h0.y, accy);
            accx = fmaf(w1, h1.x, accx); accy = fmaf(w1, h1.y, accy);
            accx = fmaf(w2, h2.x, accx); accy = fmaf(w2, h2.y, accy);
            accx = fmaf(w3, h3.x, accx); accy = fmaf(w3, h3.y, accy);
        }
        for (; j < cnt; j++) {
            int s0 = s_s[w][j];
            float w0 = wp[j * 4 + head];
            float2 h0 = *reinterpret_cast<const float2*>(g_H + (size_t)s0 * 64 + cbase);
            accx = fmaf(w0, h0.x, accx); accy = fmaf(w0, h0.y, accy);
        }
        __syncwarp();
    }

    // warp-reduce the exp sums
#pragma unroll
    for (int off = 16; off; off >>= 1) {
        sw.x += __shfl_xor_sync(0xFFFFFFFFu, sw.x, off);
        sw.y += __shfl_xor_sync(0xFFFFFFFFu, sw.y, off);
        sw.z += __shfl_xor_sync(0xFFFFFFFFu, sw.z, off);
        sw.w += __shfl_xor_sync(0xFFFFFFFFu, sw.w, off);
    }
    float sh = (head == 0) ? sw.x : (head == 1) ? sw.y : (head == 2) ? sw.z : sw.w;
    float inv = 1.f / (sh + 1e-16f);
    *reinterpret_cast<float2*>(g_A + (size_t)n * 64 + cbase) =
        make_float2(accx * inv, accy * inv);
}

// ---------------- output init + pooling + head ----------------
__global__ void init_out_kernel(float* out, const float* __restrict__ hb) {
    int g = blockIdx.x * blockDim.x + threadIdx.x;
    if (g < GG) out[g] = hb[0];
}

__global__ void pool_kernel(const float* __restrict__ b2,
                            const float* __restrict__ hw,
                            const int* __restrict__ batch,
                            float* out) {
    __shared__ float sb[64], sw[64];
    int tid = threadIdx.x;
    if (tid < 64) { sb[tid] = b2[tid]; sw[tid] = hw[tid]; }
    __syncthreads();

    long long t = (long long)blockIdx.x * blockDim.x + tid;
    int n = (int)(t >> 5);
    int lane = (int)(t & 31);
    if (n >= NN) return;

    const float* ar = g_A + (size_t)n * 64;
    float sm = fmaxf(ar[lane] + sb[lane], 0.f) * sw[lane]
             + fmaxf(ar[lane + 32] + sb[lane + 32], 0.f) * sw[lane + 32];
#pragma unroll
    for (int off = 16; off > 0; off >>= 1)
        sm += __shfl_down_sync(0xFFFFFFFFu, sm, off);
    if (lane == 0) atomicAdd(&out[batch[n]], sm);
}

// ---------------- launch ----------------
extern "C" void kernel_launch(void* const* d_in, const int* in_sizes, int n_in,
                              void* d_out, int out_size) {
    const float* x     = (const float*)d_in[0];
    const int*   ei    = (const int*)d_in[1];
    const int*   batch = (const int*)d_in[2];
    const float* W0  = (const float*)d_in[3];
    const float* as0 = (const float*)d_in[4];
    const float* ad0 = (const float*)d_in[5];
    const float* b0  = (const float*)d_in[6];
    const float* W1  = (const float*)d_in[7];
    const float* as1 = (const float*)d_in[8];
    const float* ad1 = (const float*)d_in[9];
    const float* b1  = (const float*)d_in[10];
    const float* W2  = (const float*)d_in[11];
    const float* as2 = (const float*)d_in[12];
    const float* ad2 = (const float*)d_in[13];
    const float* b2  = (const float*)d_in[14];
    const float* hw  = (const float*)d_in[15];
    const float* hb  = (const float*)d_in[16];
    float* out = (float*)d_out;

    const int EB  = (ET + 255) / 256;
    const int NB  = (NN + 255) / 256;
    const int GB  = (NN + 127) / 128;
    const int AB  = (NN + WPB - 1) / WPB;
    const int PB  = (int)(((long long)NN * 32 + 255) / 256);

    // CSR build (once)
    zero_deg_kernel<<<NB, 256>>>();
    hist_kernel<<<EB, 256>>>(ei);
    scan1_kernel<<<NBLK, 1024>>>();
    scan2_kernel<<<1, 32>>>();
    scan3_kernel<<<NB, 256>>>();
    scatter_kernel<<<EB, 256>>>(ei);

    // layer 0
    gemm_attn_kernel<128, false><<<GB, 128>>>(x, W0, as0, ad0, nullptr);
    gat_aggregate_kernel<<<AB, 256>>>();

    // layer 1 (input = g_A with bias b0 + relu)
    gemm_attn_kernel<64, true><<<GB, 128>>>(nullptr, W1, as1, ad1, b0);
    gat_aggregate_kernel<<<AB, 256>>>();

    // layer 2 (input = g_A with bias b1 + relu)
    gemm_attn_kernel<64, true><<<GB, 128>>>(nullptr, W2, as2, ad2, b1);
    gat_aggregate_kernel<<<AB, 256>>>();

    // pooling + head (bias b2 + relu fused here)
    init_out_kernel<<<(GG + 255) / 256, 256>>>(out, hb);
    pool_kernel<<<PB, 256>>>(b2, hw, batch, out);
}

// round 4
// speedup vs baseline: 2.9300x; 1.0763x over previous
#include <cuda_runtime.h>
#include <cuda_fp16.h>

#define NN 100000
#define EE 1600000
#define ET (EE + NN)
#define GG 2048
#define NBLK ((NN + 1023) / 1024)
#define WPB 8

// ---------------- scratch (device globals; no allocation) ----------------
__device__ __align__(16) __half g_Hh[(size_t)NN * 64];  // fp16 transformed features
__device__ __align__(16) float  g_A[(size_t)NN * 64];   // aggregated output
__device__ __align__(16) float  g_als[NN * 4];
__device__ __align__(16) float  g_ald[NN * 4];
__device__ int g_deg[NN];
__device__ int g_scan[NN];
__device__ int g_rowptr[NN];
__device__ int g_cursor[NN];
__device__ int g_bsum[NBLK];
__device__ int g_boff[NBLK];
__device__ int g_csrc[ET];

__device__ __forceinline__ float lrelu(float x) { return x > 0.f ? x : 0.2f * x; }

// ---------------- CSR build ----------------
__global__ void zero_deg_kernel() {
    int i = blockIdx.x * blockDim.x + threadIdx.x;
    if (i < NN) g_deg[i] = 0;
}

__global__ void hist_kernel(const int* __restrict__ ei) {
    int i = blockIdx.x * blockDim.x + threadIdx.x;
    if (i >= ET) return;
    int dst = (i < EE) ? ei[EE + i] : (i - EE);
    atomicAdd(&g_deg[dst], 1);
}

__global__ void scan1_kernel() {
    __shared__ int buf[1024];
    int t = threadIdx.x;
    int i = blockIdx.x * 1024 + t;
    int v = (i < NN) ? g_deg[i] : 0;
    buf[t] = v;
    __syncthreads();
    for (int off = 1; off < 1024; off <<= 1) {
        int add = (t >= off) ? buf[t - off] : 0;
        __syncthreads();
        buf[t] += add;
        __syncthreads();
    }
    if (i < NN) g_scan[i] = buf[t];
    if (t == 1023) g_bsum[blockIdx.x] = buf[1023];
}

__global__ void scan2_kernel() {
    __shared__ int buf[128];
    int t = threadIdx.x;
    int v = (t < NBLK) ? g_bsum[t] : 0;
    buf[t] = v;
    __syncthreads();
    for (int off = 1; off < 128; off <<= 1) {
        int add = (t >= off) ? buf[t - off] : 0;
        __syncthreads();
        buf[t] += add;
        __syncthreads();
    }
    if (t < NBLK) g_boff[t] = buf[t] - v;  // exclusive
}

__global__ void scan3_kernel() {
    int i = blockIdx.x * blockDim.x + threadIdx.x;
    if (i >= NN) return;
    int rp = g_scan[i] - g_deg[i] + g_boff[i >> 10];  // exclusive prefix
    g_rowptr[i] = rp;
    g_cursor[i] = rp;
}

__global__ void scatter_kernel(const int* __restrict__ ei) {
    int i = blockIdx.x * blockDim.x + threadIdx.x;
    if (i >= ET) return;
    int src, dst;
    if (i < EE) { src = ei[i]; dst = ei[EE + i]; }
    else        { src = i - EE; dst = i - EE; }
    int pos = atomicAdd(&g_cursor[dst], 1);
    g_csrc[pos] = src;
}

// ---------------- fused GEMM + attention logits ----------------
// h = act(xin) @ W ; als/ald = einsum(h, a_src/a_dst); g_Hh = fp16(h)
template <int FIN, bool FROM_A>
__global__ void __launch_bounds__(128)
gemm_attn_kernel(const float* __restrict__ xin_ext,
                 const float* __restrict__ W,
                 const float* __restrict__ a_src,
                 const float* __restrict__ a_dst,
                 const float* __restrict__ pbias) {
    __shared__ float Ws[FIN * 64];
    __shared__ float As[64], Ad[64];
    __shared__ float Pb[FIN];
    int tid = threadIdx.x;
    for (int i = tid; i < FIN * 64; i += 128) Ws[i] = W[i];
    if (tid < 64) { As[tid] = a_src[tid]; Ad[tid] = a_dst[tid]; }
    if (FROM_A) {
        for (int i = tid; i < FIN; i += 128) Pb[i] = pbias[i];
    }
    __syncthreads();

    int n = blockIdx.x * 128 + tid;
    if (n >= NN) return;

    float acc[64];
#pragma unroll
    for (int j = 0; j < 64; j++) acc[j] = 0.f;

    const float* xin = FROM_A ? (const float*)g_A : xin_ext;
    const float4* xr = reinterpret_cast<const float4*>(xin + (size_t)n * FIN);

    for (int k4 = 0; k4 < FIN / 4; k4++) {
        float4 xv = xr[k4];
        float xs[4] = {xv.x, xv.y, xv.z, xv.w};
#pragma unroll
        for (int u = 0; u < 4; u++) {
            float v = xs[u];
            if (FROM_A) v = fmaxf(v + Pb[k4 * 4 + u], 0.f);
            const float* wrow = &Ws[(k4 * 4 + u) * 64];
#pragma unroll
            for (int j = 0; j < 64; j++) acc[j] = fmaf(v, wrow[j], acc[j]);
        }
    }

    // write H as fp16, packed 8 halves per uint4 store
    uint4* Hr = reinterpret_cast<uint4*>(g_Hh + (size_t)n * 64);
#pragma unroll
    for (int g8 = 0; g8 < 8; g8++) {
        __half2 p0 = __floats2half2_rn(acc[8 * g8 + 0], acc[8 * g8 + 1]);
        __half2 p1 = __floats2half2_rn(acc[8 * g8 + 2], acc[8 * g8 + 3]);
        __half2 p2 = __floats2half2_rn(acc[8 * g8 + 4], acc[8 * g8 + 5]);
        __half2 p3 = __floats2half2_rn(acc[8 * g8 + 6], acc[8 * g8 + 7]);
        uint4 pk;
        pk.x = *reinterpret_cast<unsigned*>(&p0);
        pk.y = *reinterpret_cast<unsigned*>(&p1);
        pk.z = *reinterpret_cast<unsigned*>(&p2);
        pk.w = *reinterpret_cast<unsigned*>(&p3);
        Hr[g8] = pk;
    }

#pragma unroll
    for (int h = 0; h < 4; h++) {
        float ss = 0.f, dd = 0.f;
#pragma unroll
        for (int c = 0; c < 16; c++) {
            ss = fmaf(acc[h * 16 + c], As[h * 16 + c], ss);
            dd = fmaf(acc[h * 16 + c], Ad[h * 16 + c], dd);
        }
        g_als[n * 4 + h] = ss;
        g_ald[n * 4 + h] = dd;
    }
}

// ---------------- fused softmax + aggregation (gather, warp per dst node) ----
__global__ void __launch_bounds__(256) gat_aggregate_kernel() {
    __shared__ int    s_s[WPB][32];
    __shared__ float4 s_w[WPB][32];

    int w = threadIdx.x >> 5;
    int lane = threadIdx.x & 31;
    int n = blockIdx.x * WPB + w;
    if (n >= NN) return;

    int beg = g_rowptr[n];
    int deg = g_deg[n];
    float4 ad = *reinterpret_cast<const float4*>(g_ald + n * 4);

    int head = lane >> 3;          // lane owns channels (2*lane, 2*lane+1)
    float accx = 0.f, accy = 0.f;
    float4 sw;

    const __half2* Hp = reinterpret_cast<const __half2*>(g_Hh);

    if (deg <= 32) {
        // ---- fast path: single gather of als, one chunk ----
        int s_reg = 0;
        float4 a = make_float4(-1e30f, -1e30f, -1e30f, -1e30f);
        bool act = lane < deg;
        if (act) {
            s_reg = g_csrc[beg + lane];
            a = *reinterpret_cast<const float4*>(g_als + s_reg * 4);
        }
        float4 mx = a;
#pragma unroll
        for (int off = 16; off; off >>= 1) {
            mx.x = fmaxf(mx.x, __shfl_xor_sync(0xFFFFFFFFu, mx.x, off));
            mx.y = fmaxf(mx.y, __shfl_xor_sync(0xFFFFFFFFu, mx.y, off));
            mx.z = fmaxf(mx.z, __shfl_xor_sync(0xFFFFFFFFu, mx.z, off));
            mx.w = fmaxf(mx.w, __shfl_xor_sync(0xFFFFFFFFu, mx.w, off));
        }
        float m0 = lrelu(mx.x + ad.x), m1 = lrelu(mx.y + ad.y);
        float m2 = lrelu(mx.z + ad.z), m3 = lrelu(mx.w + ad.w);

        float4 wv = make_float4(0.f, 0.f, 0.f, 0.f);
        if (act) {
            wv.x = __expf(lrelu(a.x + ad.x) - m0);
            wv.y = __expf(lrelu(a.y + ad.y) - m1);
            wv.z = __expf(lrelu(a.z + ad.z) - m2);
            wv.w = __expf(lrelu(a.w + ad.w) - m3);
            s_s[w][lane] = s_reg;
            s_w[w][lane] = wv;
        }
        sw = wv;
        __syncwarp();

        const float* wp = reinterpret_cast<const float*>(&s_w[w][0]);
#pragma unroll 4
        for (int j = 0; j < deg; j++) {
            int s0 = s_s[w][j];
            float w0 = wp[j * 4 + head];
            float2 f = __half22float2(Hp[(size_t)s0 * 32 + lane]);
            accx = fmaf(w0, f.x, accx);
            accy = fmaf(w0, f.y, accy);
        }
    } else {
        // ---- general path (rare): two-pass chunked ----
        float4 mx = make_float4(-1e30f, -1e30f, -1e30f, -1e30f);
        for (int i = lane; i < deg; i += 32) {
            int s = g_csrc[beg + i];
            float4 a = *reinterpret_cast<const float4*>(g_als + s * 4);
            mx.x = fmaxf(mx.x, a.x); mx.y = fmaxf(mx.y, a.y);
            mx.z = fmaxf(mx.z, a.z); mx.w = fmaxf(mx.w, a.w);
        }
#pragma unroll
        for (int off = 16; off; off >>= 1) {
            mx.x = fmaxf(mx.x, __shfl_xor_sync(0xFFFFFFFFu, mx.x, off));
            mx.y = fmaxf(mx.y, __shfl_xor_sync(0xFFFFFFFFu, mx.y, off));
            mx.z = fmaxf(mx.z, __shfl_xor_sync(0xFFFFFFFFu, mx.z, off));
            mx.w = fmaxf(mx.w, __shfl_xor_sync(0xFFFFFFFFu, mx.w, off));
        }
        float m0 = lrelu(mx.x + ad.x), m1 = lrelu(mx.y + ad.y);
        float m2 = lrelu(mx.z + ad.z), m3 = lrelu(mx.w + ad.w);

        sw = make_float4(0.f, 0.f, 0.f, 0.f);
        for (int base = 0; base < deg; base += 32) {
            int i = base + lane;
            if (i < deg) {
                int s = g_csrc[beg + i];
                float4 a = *reinterpret_cast<const float4*>(g_als + s * 4);
                float4 wv;
                wv.x = __expf(lrelu(a.x + ad.x) - m0);
                wv.y = __expf(lrelu(a.y + ad.y) - m1);
                wv.z = __expf(lrelu(a.z + ad.z) - m2);
                wv.w = __expf(lrelu(a.w + ad.w) - m3);
                sw.x += wv.x; sw.y += wv.y; sw.z += wv.z; sw.w += wv.w;
                s_s[w][lane] = s;
                s_w[w][lane] = wv;
            }
            __syncwarp();
            int cnt = min(32, deg - base);
            const float* wp = reinterpret_cast<const float*>(&s_w[w][0]);
#pragma unroll 4
            for (int j = 0; j < cnt; j++) {
                int s0 = s_s[w][j];
                float w0 = wp[j * 4 + head];
                float2 f = __half22float2(Hp[(size_t)s0 * 32 + lane]);
                accx = fmaf(w0, f.x, accx);
                accy = fmaf(w0, f.y, accy);
            }
            __syncwarp();
        }
    }

    // warp-reduce the exp sums
#pragma unroll
    for (int off = 16; off; off >>= 1) {
        sw.x += __shfl_xor_sync(0xFFFFFFFFu, sw.x, off);
        sw.y += __shfl_xor_sync(0xFFFFFFFFu, sw.y, off);
        sw.z += __shfl_xor_sync(0xFFFFFFFFu, sw.z, off);
        sw.w += __shfl_xor_sync(0xFFFFFFFFu, sw.w, off);
    }
    float sh = (head == 0) ? sw.x : (head == 1) ? sw.y : (head == 2) ? sw.z : sw.w;
    float inv = 1.f / (sh + 1e-16f);
    *reinterpret_cast<float2*>(g_A + (size_t)n * 64 + 2 * lane) =
        make_float2(accx * inv, accy * inv);
}

// ---------------- output init + pooling + head ----------------
__global__ void init_out_kernel(float* out, const float* __restrict__ hb) {
    int g = blockIdx.x * blockDim.x + threadIdx.x;
    if (g < GG) out[g] = hb[0];
}

__global__ void pool_kernel(const float* __restrict__ b2,
                            const float* __restrict__ hw,
                            const int* __restrict__ batch,
                            float* out) {
    __shared__ float sb[64], sw[64];
    int tid = threadIdx.x;
    if (tid < 64) { sb[tid] = b2[tid]; sw[tid] = hw[tid]; }
    __syncthreads();

    long long t = (long long)blockIdx.x * blockDim.x + tid;
    int n = (int)(t >> 5);
    int lane = (int)(t & 31);
    if (n >= NN) return;

    const float* ar = g_A + (size_t)n * 64;
    float sm = fmaxf(ar[lane] + sb[lane], 0.f) * sw[lane]
             + fmaxf(ar[lane + 32] + sb[lane + 32], 0.f) * sw[lane + 32];
#pragma unroll
    for (int off = 16; off > 0; off >>= 1)
        sm += __shfl_down_sync(0xFFFFFFFFu, sm, off);
    if (lane == 0) atomicAdd(&out[batch[n]], sm);
}

// ---------------- launch ----------------
extern "C" void kernel_launch(void* const* d_in, const int* in_sizes, int n_in,
                              void* d_out, int out_size) {
    const float* x     = (const float*)d_in[0];
    const int*   ei    = (const int*)d_in[1];
    const int*   batch = (const int*)d_in[2];
    const float* W0  = (const float*)d_in[3];
    const float* as0 = (const float*)d_in[4];
    const float* ad0 = (const float*)d_in[5];
    const float* b0  = (const float*)d_in[6];
    const float* W1  = (const float*)d_in[7];
    const float* as1 = (const float*)d_in[8];
    const float* ad1 = (const float*)d_in[9];
    const float* b1  = (const float*)d_in[10];
    const float* W2  = (const float*)d_in[11];
    const float* as2 = (const float*)d_in[12];
    const float* ad2 = (const float*)d_in[13];
    const float* b2  = (const float*)d_in[14];
    const float* hw  = (const float*)d_in[15];
    const float* hb  = (const float*)d_in[16];
    float* out = (float*)d_out;

    const int EB = (ET + 255) / 256;
    const int NB = (NN + 255) / 256;
    const int GB = (NN + 127) / 128;
    const int AB = (NN + WPB - 1) / WPB;
    const int PB = (int)(((long long)NN * 32 + 255) / 256);

    // CSR build (once)
    zero_deg_kernel<<<NB, 256>>>();
    hist_kernel<<<EB, 256>>>(ei);
    scan1_kernel<<<NBLK, 1024>>>();
    scan2_kernel<<<1, 128>>>();
    scan3_kernel<<<NB, 256>>>();
    scatter_kernel<<<EB, 256>>>(ei);

    // layer 0
    gemm_attn_kernel<128, false><<<GB, 128>>>(x, W0, as0, ad0, nullptr);
    gat_aggregate_kernel<<<AB, 256>>>();

    // layer 1 (input = g_A with bias b0 + relu)
    gemm_attn_kernel<64, true><<<GB, 128>>>(nullptr, W1, as1, ad1, b0);
    gat_aggregate_kernel<<<AB, 256>>>();

    // layer 2 (input = g_A with bias b1 + relu)
    gemm_attn_kernel<64, true><<<GB, 128>>>(nullptr, W2, as2, ad2, b1);
    gat_aggregate_kernel<<<AB, 256>>>();

    // pooling + head (bias b2 + relu fused here)
    init_out_kernel<<<(GG + 255) / 256, 256>>>(out, hb);
    pool_kernel<<<PB, 256>>>(b2, hw, batch, out);
}

// round 5
// speedup vs baseline: 2.9885x; 1.0200x over previous
#include <cuda_runtime.h>
#include <cuda_fp16.h>

#define NN 100000
#define EE 1600000
#define ET (EE + NN)
#define GG 2048
#define NBLK ((NN + 1023) / 1024)
#define WPB 8

typedef unsigned long long u64;

// ---------------- scratch (device globals; no allocation) ----------------
__device__ __align__(16) __half g_Hh[(size_t)NN * 64];  // fp16 transformed features
__device__ __align__(16) float  g_A[(size_t)NN * 64];   // aggregated output
__device__ __align__(16) float  g_als[NN * 4];
__device__ __align__(16) float  g_ald[NN * 4];
__device__ int g_deg[NN];       // zero-initialized at load; re-zeroed by pool_kernel
__device__ int g_scan[NN];
__device__ int g_rowptr[NN];
__device__ int g_cursor[NN];
__device__ int g_bsum[NBLK];
__device__ int g_csrc[ET];

__device__ __forceinline__ float lrelu(float x) { return x > 0.f ? x : 0.2f * x; }

// f32x2 packed helpers (Blackwell FFMA2)
__device__ __forceinline__ u64 pack2(float x, float y) {
    u64 r; asm("mov.b64 %0,{%1,%2};" : "=l"(r) : "f"(x), "f"(y)); return r;
}
__device__ __forceinline__ void fma2(u64& d, u64 a, u64 b) {
    asm("fma.rn.f32x2 %0,%1,%2,%0;" : "+l"(d) : "l"(a), "l"(b));
}
__device__ __forceinline__ float2 unpack2(u64 v) {
    float x, y; asm("mov.b64 {%0,%1},%2;" : "=f"(x), "=f"(y) : "l"(v));
    return make_float2(x, y);
}

// ---------------- CSR build ----------------
// NOTE: g_deg must be zero at entry. It is zero-initialized at module load and
// re-zeroed at the END of every kernel_launch sequence (in pool_kernel), so the
// invariant holds for the correctness run, capture, and every graph replay.
__global__ void hist_kernel(const int* __restrict__ ei) {
    int i = blockIdx.x * blockDim.x + threadIdx.x;
    if (i >= ET) return;
    int dst = (i < EE) ? ei[EE + i] : (i - EE);
    atomicAdd(&g_deg[dst], 1);
}

__global__ void scan1_kernel() {
    __shared__ int buf[1024];
    int t = threadIdx.x;
    int i = blockIdx.x * 1024 + t;
    int v = (i < NN) ? g_deg[i] : 0;
    buf[t] = v;
    __syncthreads();
    for (int off = 1; off < 1024; off <<= 1) {
        int add = (t >= off) ? buf[t - off] : 0;
        __syncthreads();
        buf[t] += add;
        __syncthreads();
    }
    if (i < NN) g_scan[i] = buf[t];
    if (t == 1023) g_bsum[blockIdx.x] = buf[1023];
}

// fused scan2+scan3: each block re-scans the 98 block sums locally (cheap)
__global__ void scan3_kernel() {
    __shared__ int sb[128];
    __shared__ int ex[128];
    int t = threadIdx.x;
    int v0 = 0;
    if (t < 128) {
        v0 = (t < NBLK) ? g_bsum[t] : 0;
        sb[t] = v0;
    }
    __syncthreads();
    for (int off = 1; off < 128; off <<= 1) {
        int add = (t < 128 && t >= off) ? sb[t - off] : 0;
        __syncthreads();
        if (t < 128) sb[t] += add;
        __syncthreads();
    }
    if (t < 128) ex[t] = sb[t] - v0;  // exclusive
    __syncthreads();

    int i = blockIdx.x * blockDim.x + t;
    if (i >= NN) return;
    int rp = g_scan[i] - g_deg[i] + ex[i >> 10];
    g_rowptr[i] = rp;
    g_cursor[i] = rp;
}

__global__ void scatter_kernel(const int* __restrict__ ei) {
    int i = blockIdx.x * blockDim.x + threadIdx.x;
    if (i >= ET) return;
    int src, dst;
    if (i < EE) { src = ei[i]; dst = ei[EE + i]; }
    else        { src = i - EE; dst = i - EE; }
    int pos = atomicAdd(&g_cursor[dst], 1);
    g_csrc[pos] = src;
}

// ---------------- fused GEMM + attention logits (f32x2 packed FMA) ---------
template <int FIN, bool FROM_A>
__global__ void __launch_bounds__(128)
gemm_attn_kernel(const float* __restrict__ xin_ext,
                 const float* __restrict__ W,
                 const float* __restrict__ a_src,
                 const float* __restrict__ a_dst,
                 const float* __restrict__ pbias) {
    __shared__ __align__(16) float Ws[FIN * 64];
    __shared__ float As[64], Ad[64];
    __shared__ float Pb[FIN];
    int tid = threadIdx.x;
    for (int i = tid; i < FIN * 64; i += 128) Ws[i] = W[i];
    if (tid < 64) { As[tid] = a_src[tid]; Ad[tid] = a_dst[tid]; }
    if (FROM_A) {
        for (int i = tid; i < FIN; i += 128) Pb[i] = pbias[i];
    }
    __syncthreads();

    int n = blockIdx.x * 128 + tid;
    if (n >= NN) return;

    u64 acc[32];
#pragma unroll
    for (int j = 0; j < 32; j++) acc[j] = 0ull;  // two packed 0.0f

    const float* xin = FROM_A ? (const float*)g_A : xin_ext;
    const float4* xr = reinterpret_cast<const float4*>(xin + (size_t)n * FIN);

    for (int k4 = 0; k4 < FIN / 4; k4++) {
        float4 xv = xr[k4];
        float xs[4] = {xv.x, xv.y, xv.z, xv.w};
#pragma unroll
        for (int u = 0; u < 4; u++) {
            float v = xs[u];
            if (FROM_A) v = fmaxf(v + Pb[k4 * 4 + u], 0.f);
            u64 vv = pack2(v, v);
            const double2* wrow =
                reinterpret_cast<const double2*>(&Ws[(k4 * 4 + u) * 64]);
#pragma unroll
            for (int j4 = 0; j4 < 16; j4++) {
                double2 wd = wrow[j4];
                fma2(acc[2 * j4 + 0], vv, (u64)__double_as_longlong(wd.x));
                fma2(acc[2 * j4 + 1], vv, (u64)__double_as_longlong(wd.y));
            }
        }
    }

    float accf[64];
#pragma unroll
    for (int j2 = 0; j2 < 32; j2++) {
        float2 f = unpack2(acc[j2]);
        accf[2 * j2] = f.x;
        accf[2 * j2 + 1] = f.y;
    }

    // write H as fp16, packed 8 halves per uint4 store
    uint4* Hr = reinterpret_cast<uint4*>(g_Hh + (size_t)n * 64);
#pragma unroll
    for (int g8 = 0; g8 < 8; g8++) {
        __half2 p0 = __floats2half2_rn(accf[8 * g8 + 0], accf[8 * g8 + 1]);
        __half2 p1 = __floats2half2_rn(accf[8 * g8 + 2], accf[8 * g8 + 3]);
        __half2 p2 = __floats2half2_rn(accf[8 * g8 + 4], accf[8 * g8 + 5]);
        __half2 p3 = __floats2half2_rn(accf[8 * g8 + 6], accf[8 * g8 + 7]);
        uint4 pk;
        pk.x = *reinterpret_cast<unsigned*>(&p0);
        pk.y = *reinterpret_cast<unsigned*>(&p1);
        pk.z = *reinterpret_cast<unsigned*>(&p2);
        pk.w = *reinterpret_cast<unsigned*>(&p3);
        Hr[g8] = pk;
    }

#pragma unroll
    for (int h = 0; h < 4; h++) {
        float ss = 0.f, dd = 0.f;
#pragma unroll
        for (int c = 0; c < 16; c++) {
            ss = fmaf(accf[h * 16 + c], As[h * 16 + c], ss);
            dd = fmaf(accf[h * 16 + c], Ad[h * 16 + c], dd);
        }
        g_als[n * 4 + h] = ss;
        g_ald[n * 4 + h] = dd;
    }
}

// ---------------- fused softmax + aggregation (gather, warp per dst node) ----
__global__ void __launch_bounds__(256) gat_aggregate_kernel() {
    __shared__ int    s_s[WPB][32];
    __shared__ float4 s_w[WPB][32];

    int w = threadIdx.x >> 5;
    int lane = threadIdx.x & 31;
    int n = blockIdx.x * WPB + w;
    if (n >= NN) return;

    int beg = g_rowptr[n];
    int deg = g_deg[n];
    float4 ad = *reinterpret_cast<const float4*>(g_ald + n * 4);

    int head = lane >> 3;          // lane owns channels (2*lane, 2*lane+1)
    float accx = 0.f, accy = 0.f;
    float4 sw;

    const __half2* Hp = reinterpret_cast<const __half2*>(g_Hh);

    if (deg <= 32) {
        // ---- fast path: single gather of als, one chunk ----
        int s_reg = 0;
        float4 a = make_float4(-1e30f, -1e30f, -1e30f, -1e30f);
        bool act = lane < deg;
        if (act) {
            s_reg = g_csrc[beg + lane];
            a = *reinterpret_cast<const float4*>(g_als + s_reg * 4);
        }
        float4 mx = a;
#pragma unroll
        for (int off = 16; off; off >>= 1) {
            mx.x = fmaxf(mx.x, __shfl_xor_sync(0xFFFFFFFFu, mx.x, off));
            mx.y = fmaxf(mx.y, __shfl_xor_sync(0xFFFFFFFFu, mx.y, off));
            mx.z = fmaxf(mx.z, __shfl_xor_sync(0xFFFFFFFFu, mx.z, off));
            mx.w = fmaxf(mx.w, __shfl_xor_sync(0xFFFFFFFFu, mx.w, off));
        }
        float m0 = lrelu(mx.x + ad.x), m1 = lrelu(mx.y + ad.y);
        float m2 = lrelu(mx.z + ad.z), m3 = lrelu(mx.w + ad.w);

        float4 wv = make_float4(0.f, 0.f, 0.f, 0.f);
        if (act) {
            wv.x = __expf(lrelu(a.x + ad.x) - m0);
            wv.y = __expf(lrelu(a.y + ad.y) - m1);
            wv.z = __expf(lrelu(a.z + ad.z) - m2);
            wv.w = __expf(lrelu(a.w + ad.w) - m3);
            s_s[w][lane] = s_reg;
            s_w[w][lane] = wv;
        }
        sw = wv;
        __syncwarp();

        const float* wp = reinterpret_cast<const float*>(&s_w[w][0]);
#pragma unroll 8
        for (int j = 0; j < deg; j++) {
            int s0 = s_s[w][j];
            float w0 = wp[j * 4 + head];
            float2 f = __half22float2(Hp[(size_t)s0 * 32 + lane]);
            accx = fmaf(w0, f.x, accx);
            accy = fmaf(w0, f.y, accy);
        }
    } else {
        // ---- general path (rare): two-pass chunked ----
        float4 mx = make_float4(-1e30f, -1e30f, -1e30f, -1e30f);
        for (int i = lane; i < deg; i += 32) {
            int s = g_csrc[beg + i];
            float4 a = *reinterpret_cast<const float4*>(g_als + s * 4);
            mx.x = fmaxf(mx.x, a.x); mx.y = fmaxf(mx.y, a.y);
            mx.z = fmaxf(mx.z, a.z); mx.w = fmaxf(mx.w, a.w);
        }
#pragma unroll
        for (int off = 16; off; off >>= 1) {
            mx.x = fmaxf(mx.x, __shfl_xor_sync(0xFFFFFFFFu, mx.x, off));
            mx.y = fmaxf(mx.y, __shfl_xor_sync(0xFFFFFFFFu, mx.y, off));
            mx.z = fmaxf(mx.z, __shfl_xor_sync(0xFFFFFFFFu, mx.z, off));
            mx.w = fmaxf(mx.w, __shfl_xor_sync(0xFFFFFFFFu, mx.w, off));
        }
        float m0 = lrelu(mx.x + ad.x), m1 = lrelu(mx.y + ad.y);
        float m2 = lrelu(mx.z + ad.z), m3 = lrelu(mx.w + ad.w);

        sw = make_float4(0.f, 0.f, 0.f, 0.f);
        for (int base = 0; base < deg; base += 32) {
            int i = base + lane;
            if (i < deg) {
                int s = g_csrc[beg + i];
                float4 a = *reinterpret_cast<const float4*>(g_als + s * 4);
                float4 wv;
                wv.x = __expf(lrelu(a.x + ad.x) - m0);
                wv.y = __expf(lrelu(a.y + ad.y) - m1);
                wv.z = __expf(lrelu(a.z + ad.z) - m2);
                wv.w = __expf(lrelu(a.w + ad.w) - m3);
                sw.x += wv.x; sw.y += wv.y; sw.z += wv.z; sw.w += wv.w;
                s_s[w][lane] = s;
                s_w[w][lane] = wv;
            }
            __syncwarp();
            int cnt = min(32, deg - base);
            const float* wp = reinterpret_cast<const float*>(&s_w[w][0]);
#pragma unroll 8
            for (int j = 0; j < cnt; j++) {
                int s0 = s_s[w][j];
                float w0 = wp[j * 4 + head];
                float2 f = __half22float2(Hp[(size_t)s0 * 32 + lane]);
                accx = fmaf(w0, f.x, accx);
                accy = fmaf(w0, f.y, accy);
            }
            __syncwarp();
        }
    }

    // warp-reduce the exp sums
#pragma unroll
    for (int off = 16; off; off >>= 1) {
        sw.x += __shfl_xor_sync(0xFFFFFFFFu, sw.x, off);
        sw.y += __shfl_xor_sync(0xFFFFFFFFu, sw.y, off);
        sw.z += __shfl_xor_sync(0xFFFFFFFFu, sw.z, off);
        sw.w += __shfl_xor_sync(0xFFFFFFFFu, sw.w, off);
    }
    float sh = (head == 0) ? sw.x : (head == 1) ? sw.y : (head == 2) ? sw.z : sw.w;
    float inv = 1.f / (sh + 1e-16f);
    *reinterpret_cast<float2*>(g_A + (size_t)n * 64 + 2 * lane) =
        make_float2(accx * inv, accy * inv);
}

// ---------------- output init + pooling + head ----------------
__global__ void init_out_kernel(float* out, const float* __restrict__ hb) {
    int g = blockIdx.x * blockDim.x + threadIdx.x;
    if (g < GG) out[g] = hb[0];
}

__global__ void pool_kernel(const float* __restrict__ b2,
                            const float* __restrict__ hw,
                            const int* __restrict__ batch,
                            float* out) {
    __shared__ float sb[64], sw[64];
    int tid = threadIdx.x;
    if (tid < 64) { sb[tid] = b2[tid]; sw[tid] = hw[tid]; }
    __syncthreads();

    long long t = (long long)blockIdx.x * blockDim.x + tid;
    int n = (int)(t >> 5);
    int lane = (int)(t & 31);
    if (n >= NN) return;

    const float* ar = g_A + (size_t)n * 64;
    float sm = fmaxf(ar[lane] + sb[lane], 0.f) * sw[lane]
             + fmaxf(ar[lane + 32] + sb[lane + 32], 0.f) * sw[lane + 32];
#pragma unroll
    for (int off = 16; off > 0; off >>= 1)
        sm += __shfl_down_sync(0xFFFFFFFFu, sm, off);
    if (lane == 0) {
        atomicAdd(&out[batch[n]], sm);
        g_deg[n] = 0;   // restore CSR-build invariant for the next replay
    }
}

// ---------------- launch ----------------
extern "C" void kernel_launch(void* const* d_in, const int* in_sizes, int n_in,
                              void* d_out, int out_size) {
    const float* x     = (const float*)d_in[0];
    const int*   ei    = (const int*)d_in[1];
    const int*   batch = (const int*)d_in[2];
    const float* W0  = (const float*)d_in[3];
    const float* as0 = (const float*)d_in[4];
    const float* ad0 = (const float*)d_in[5];
    const float* b0  = (const float*)d_in[6];
    const float* W1  = (const float*)d_in[7];
    const float* as1 = (const float*)d_in[8];
    const float* ad1 = (const float*)d_in[9];
    const float* b1  = (const float*)d_in[10];
    const float* W2  = (const float*)d_in[11];
    const float* as2 = (const float*)d_in[12];
    const float* ad2 = (const float*)d_in[13];
    const float* b2  = (const float*)d_in[14];
    const float* hw  = (const float*)d_in[15];
    const float* hb  = (const float*)d_in[16];
    float* out = (float*)d_out;

    const int EB = (ET + 255) / 256;
    const int NB = (NN + 255) / 256;
    const int GB = (NN + 127) / 128;
    const int AB = (NN + WPB - 1) / WPB;
    const int PB = (int)(((long long)NN * 32 + 255) / 256);

    // CSR build; gemm0 placed at launch index 3 so ncu captures it
    hist_kernel<<<EB, 256>>>(ei);                                   // 0
    scan1_kernel<<<NBLK, 1024>>>();                                 // 1
    scan3_kernel<<<NB, 256>>>();                                    // 2
    gemm_attn_kernel<128, false><<<GB, 128>>>(x, W0, as0, ad0, nullptr); // 3
    scatter_kernel<<<EB, 256>>>(ei);                                // 4

    // layer 0 aggregate
    gat_aggregate_kernel<<<AB, 256>>>();

    // layer 1 (input = g_A with bias b0 + relu)
    gemm_attn_kernel<64, true><<<GB, 128>>>(nullptr, W1, as1, ad1, b0);
    gat_aggregate_kernel<<<AB, 256>>>();

    // layer 2 (input = g_A with bias b1 + relu)
    gemm_attn_kernel<64, true><<<GB, 128>>>(nullptr, W2, as2, ad2, b1);
    gat_aggregate_kernel<<<AB, 256>>>();

    // pooling + head (bias b2 + relu fused; also re-zeros g_deg)
    init_out_kernel<<<(GG + 255) / 256, 256>>>(out, hb);
    pool_kernel<<<PB, 256>>>(b2, hw, batch, out);
}